// round 4
// baseline (speedup 1.0000x reference)
#include <cuda_runtime.h>

#define NN 100000
#define EE 1600000

// Scratch (allocation-free rule: __device__ globals)
__device__ float g_kw [NN * 128];   // interleaved: [n][0:64]=k row, [n][64:128]=hw row
__device__ float g_q  [NN * 64];
__device__ int   g_cnt [NN];
__device__ int   g_roff[NN + 1];
__device__ int   g_cur [NN];
__device__ int   g_bsum[512];
__device__ int   g_boff[512];
__device__ int   g_esrc[EE];

// ---------------------------------------------------------------------------
// Kernel 1: k = h@Wk, q = h@Wq, hw = h@W  (three 64x64 projections, fused)
// PLUS the dst-histogram for the CSR build: the histogram is pure memory ops
// (LDG + RED) and hides completely under the FMA-bound gemm.
// ---------------------------------------------------------------------------
__global__ __launch_bounds__(256) void gemm3_hist_kernel(
    const float* __restrict__ h,
    const float* __restrict__ Wk,
    const float* __restrict__ Wq,
    const float* __restrict__ Ww,
    const int*   __restrict__ dst,
    int N, int E)
{
    __shared__ float sWk[64 * 68];
    __shared__ float sWq[64 * 68];
    __shared__ float sWw[64 * 68];
    __shared__ float sh [32 * 68];

    const int tid = threadIdx.x;

    // --- histogram slice for this block (fire-and-forget L2 reductions) ---
    {
        const int eslice = (E + gridDim.x - 1) / gridDim.x;
        const int e0 = blockIdx.x * eslice;
        const int e1 = (e0 + eslice < E) ? e0 + eslice : E;
        for (int i = e0 + tid; i < e1; i += 256)
            atomicAdd(&g_cnt[dst[i]], 1);
    }

    // --- gemm tile ---
    for (int idx = tid; idx < 64 * 64; idx += 256) {
        int i = idx >> 6, c = idx & 63;
        sWk[c * 68 + i] = Wk[idx];
        sWq[c * 68 + i] = Wq[idx];
        sWw[c * 68 + i] = Ww[idx];
    }
    const int base = blockIdx.x * 32;
    for (int idx = tid; idx < 32 * 64; idx += 256) {
        int n = idx >> 6, c = idx & 63;
        int gn = base + n;
        sh[n * 68 + c] = (gn < N) ? h[(size_t)gn * 64 + c] : 0.f;
    }
    __syncthreads();

    const int grp = tid >> 6;
    const int col = tid & 63;

    float ak[8], aq[8], aw[8];
#pragma unroll
    for (int n = 0; n < 8; n++) { ak[n] = aq[n] = aw[n] = 0.f; }

    const float4* wk4 = (const float4*)(sWk + col * 68);
    const float4* wq4 = (const float4*)(sWq + col * 68);
    const float4* ww4 = (const float4*)(sWw + col * 68);

#pragma unroll
    for (int i4 = 0; i4 < 16; i4++) {
        const float4 wk = wk4[i4];
        const float4 wq = wq4[i4];
        const float4 ww = ww4[i4];
#pragma unroll
        for (int n = 0; n < 8; n++) {
            const float4 hv = *(const float4*)(sh + (grp * 8 + n) * 68 + i4 * 4);
            ak[n] += hv.x * wk.x + hv.y * wk.y + hv.z * wk.z + hv.w * wk.w;
            aq[n] += hv.x * wq.x + hv.y * wq.y + hv.z * wq.z + hv.w * wq.w;
            aw[n] += hv.x * ww.x + hv.y * ww.y + hv.z * ww.z + hv.w * ww.w;
        }
    }

#pragma unroll
    for (int n = 0; n < 8; n++) {
        int gn = base + grp * 8 + n;
        if (gn < N) {
            g_kw[(size_t)gn * 128 + col]      = ak[n];
            g_kw[(size_t)gn * 128 + 64 + col] = aw[n];
            g_q [(size_t)gn * 64 + col]       = aq[n];
        }
    }
}

// ---------------------------------------------------------------------------
// CSR: shuffle-based two-level exclusive scan, then scatter
// ---------------------------------------------------------------------------
__global__ __launch_bounds__(256) void scan1_kernel(int N)
{
    __shared__ int wsum[8];
    const int t = threadIdx.x, lane = t & 31, wd = t >> 5;
    const int i = blockIdx.x * 256 + t;
    const int v = (i < N) ? g_cnt[i] : 0;
    int x = v;
#pragma unroll
    for (int off = 1; off < 32; off <<= 1) {
        int y = __shfl_up_sync(0xffffffffu, x, off);
        if (lane >= off) x += y;
    }
    if (lane == 31) wsum[wd] = x;
    __syncthreads();
    if (t < 8) {
        int w = wsum[t];
        int xs = w;
#pragma unroll
        for (int off = 1; off < 8; off <<= 1) {
            int y = __shfl_up_sync(0x000000ffu, xs, off);
            if (t >= off) xs += y;
        }
        wsum[t] = xs - w;                       // exclusive warp offset
        if (t == 7) g_bsum[blockIdx.x] = xs;    // block total
    }
    __syncthreads();
    if (i < N) g_roff[i] = x - v + wsum[wd];
}

__global__ __launch_bounds__(512) void scan2_kernel(int nb)
{
    __shared__ int wsum[16];
    const int t = threadIdx.x, lane = t & 31, wd = t >> 5;
    const int v = (t < nb) ? g_bsum[t] : 0;
    int x = v;
#pragma unroll
    for (int off = 1; off < 32; off <<= 1) {
        int y = __shfl_up_sync(0xffffffffu, x, off);
        if (lane >= off) x += y;
    }
    if (lane == 31) wsum[wd] = x;
    __syncthreads();
    if (t < 16) {
        int w = wsum[t];
        int xs = w;
#pragma unroll
        for (int off = 1; off < 16; off <<= 1) {
            int y = __shfl_up_sync(0x0000ffffu, xs, off);
            if (t >= off) xs += y;
        }
        wsum[t] = xs - w;
    }
    __syncthreads();
    if (t < nb) g_boff[t] = x - v + wsum[wd];
}

__global__ void scan3_kernel(int N, int E)
{
    int i = blockIdx.x * blockDim.x + threadIdx.x;
    if (i < N) {
        int r = g_roff[i] + g_boff[i >> 8];
        g_roff[i] = r;
        g_cur[i]  = r;
    }
    if (i == 0) g_roff[N] = E;
}

__global__ void scatter_kernel(const int* __restrict__ src,
                               const int* __restrict__ dst, int E)
{
    int i = blockIdx.x * blockDim.x + threadIdx.x;
    if (i < E) {
        int p = atomicAdd(&g_cur[dst[i]], 1);
        g_esrc[p] = src[i];
    }
}

// ---------------------------------------------------------------------------
// Fused edge-softmax + aggregation. One warp per destination node.
// Lane = head(2b)*8 + feature-chunk(3b). After the 3-step xor reduce every
// lane of an 8-lane group holds its head's dot -> no broadcast shuffles; z
// accumulates redundantly per lane. Single output write, bias + 1/z folded.
// ---------------------------------------------------------------------------
__global__ __launch_bounds__(256) void gather_kernel(
    const float* __restrict__ b,
    float* __restrict__ out,
    int N)
{
    const int n    = (blockIdx.x * 256 + threadIdx.x) >> 5;
    const int lane = threadIdx.x & 31;
    if (n >= N) return;
    const int hh = lane >> 3;   // head
    const int cc = lane & 7;    // 8-feature chunk within head

    const float2 q2 = ((const float2*)(g_q + (size_t)n * 64))[lane];
    const int p0 = g_roff[n];
    const int p1 = g_roff[n + 1];

    float4 accA = make_float4(0.f, 0.f, 0.f, 0.f), accB = accA;
    float z = 0.f;

    if (p0 < p1) {
        int s = g_esrc[p0];
        const float* row = g_kw + (size_t)s * 128;
        float2 k2 = ((const float2*)row)[lane];
        float4 hA = ((const float4*)(row + 64))[cc * 2];
        float4 hB = ((const float4*)(row + 64))[cc * 2 + 1];

        for (int p = p0; p < p1; p++) {
            const float2 k2c = k2;
            const float4 hAc = hA, hBc = hB;
            if (p + 1 < p1) {
                int sn = g_esrc[p + 1];
                const float* rn = g_kw + (size_t)sn * 128;
                k2 = ((const float2*)rn)[lane];
                hA = ((const float4*)(rn + 64))[cc * 2];
                hB = ((const float4*)(rn + 64))[cc * 2 + 1];
            }

            float prod = k2c.x * q2.x + k2c.y * q2.y;
            prod += __shfl_xor_sync(0xffffffffu, prod, 4);
            prod += __shfl_xor_sync(0xffffffffu, prod, 2);
            prod += __shfl_xor_sync(0xffffffffu, prod, 1);
            const float e = __expf(prod);      // per-head value, in all 8 lanes

            z += e;
            accA.x += e * hAc.x; accA.y += e * hAc.y;
            accA.z += e * hAc.z; accA.w += e * hAc.w;
            accB.x += e * hBc.x; accB.y += e * hBc.y;
            accB.z += e * hBc.z; accB.w += e * hBc.w;
        }
    }

    const float inv = (z > 0.f) ? 1.f / z : 0.f;
    const float4 b0 = ((const float4*)b)[cc * 2];
    const float4 b1 = ((const float4*)b)[cc * 2 + 1];

    float* op = out + (size_t)n * 256 + hh * 64 + cc * 8;
    ((float4*)op)[0] = make_float4(accA.x * inv + b0.x, accA.y * inv + b0.y,
                                   accA.z * inv + b0.z, accA.w * inv + b0.w);
    ((float4*)op)[1] = make_float4(accB.x * inv + b1.x, accB.y * inv + b1.y,
                                   accB.z * inv + b1.z, accB.w * inv + b1.w);
}

// ---------------------------------------------------------------------------
extern "C" void kernel_launch(void* const* d_in, const int* in_sizes, int n_in,
                              void* d_out, int out_size)
{
    const float* h   = (const float*)d_in[0];
    const int*   src = (const int*)  d_in[1];
    const int*   dst = (const int*)  d_in[2];
    const float* Wk  = (const float*)d_in[3];
    const float* Wq  = (const float*)d_in[4];
    const float* Ww  = (const float*)d_in[5];
    const float* b   = (const float*)d_in[6];
    float*       out = (float*)d_out;

    const int N  = in_sizes[0] / 64;
    const int E  = in_sizes[1];
    const int nb = (N + 255) / 256;

    // Symbol address resolved once on the (uncaptured) correctness call.
    static void* cnt_ptr = nullptr;
    if (cnt_ptr == nullptr) cudaGetSymbolAddress(&cnt_ptr, g_cnt);

    cudaMemsetAsync(cnt_ptr, 0, (size_t)N * sizeof(int));
    gemm3_hist_kernel<<<(N + 31) / 32, 256>>>(h, Wk, Wq, Ww, dst, N, E);
    scan1_kernel<<<nb, 256>>>(N);
    scan2_kernel<<<1, 512>>>(nb);
    scan3_kernel<<<(N + 255) / 256, 256>>>(N, E);
    scatter_kernel<<<(E + 255) / 256, 256>>>(src, dst, E);
    gather_kernel<<<(N + 7) / 8, 256>>>(b, out, N);
}

// round 5
// speedup vs baseline: 1.2041x; 1.2041x over previous
#include <cuda_runtime.h>

#define NN 100000
#define EE 1600000

// Scratch (allocation-free rule: __device__ globals)
__device__ float g_kw  [NN * 128];  // interleaved: [n][0:64]=k row, [n][64:128]=hw row
__device__ float g_q   [NN * 64];
__device__ int   g_cnt [NN];
__device__ int   g_roff[NN + 1];
__device__ int   g_cur [NN];
__device__ int   g_state[512];      // decoupled-lookback block state
__device__ int   g_esrc[EE];

// ---- tf32 helpers ----------------------------------------------------------
__device__ __forceinline__ unsigned to_tf32(float x)
{
    unsigned r; asm("cvt.rna.tf32.f32 %0, %1;" : "=r"(r) : "f"(x)); return r;
}
__device__ __forceinline__ void mma_tf32(float4& d, const unsigned* a, const unsigned* b)
{
    asm volatile(
        "mma.sync.aligned.m16n8k8.row.col.f32.tf32.tf32.f32 "
        "{%0,%1,%2,%3}, {%4,%5,%6,%7}, {%8,%9}, {%0,%1,%2,%3};"
        : "+f"(d.x), "+f"(d.y), "+f"(d.z), "+f"(d.w)
        : "r"(a[0]), "r"(a[1]), "r"(a[2]), "r"(a[3]), "r"(b[0]), "r"(b[1]));
}

// ---------------------------------------------------------------------------
// Kernel 1: k = h@Wk, q = h@Wq, hw = h@W via 3xTF32 tensor-core MMA
// (fp32-class accuracy), PLUS the dst-histogram (RED ops hide under MMA).
// Block: 192 threads = 6 warps; warp = (matrix sel 0..2) x (m-half 0..1).
// 32 nodes per block. Smem strides of 72 words -> conflict-free fragment LDS.
// ---------------------------------------------------------------------------
__global__ __launch_bounds__(192) void gemm_mma_hist_kernel(
    const float* __restrict__ h,
    const float* __restrict__ Wk,
    const float* __restrict__ Wq,
    const float* __restrict__ Ww,
    const int*   __restrict__ dst,
    int N, int E)
{
    __shared__ float sA[32 * 72];        // sA[node][kdim]
    __shared__ float sW[3 * 64 * 72];    // sW[sel][kdim][col]

    const int tid = threadIdx.x;

    // --- histogram slice (fire-and-forget L2 reductions) ---
    {
        const int eslice = (E + gridDim.x - 1) / gridDim.x;
        const int e0 = blockIdx.x * eslice;
        const int e1 = (e0 + eslice < E) ? e0 + eslice : E;
        for (int i = e0 + tid; i < e1; i += 192)
            atomicAdd(&g_cnt[dst[i]], 1);
    }

    // --- stage weights: sW[sel][i][c] = W[i*64+c] ---
    for (int idx = tid; idx < 64 * 64; idx += 192) {
        const int i = idx >> 6, c = idx & 63;
        sW[0 * 64 * 72 + i * 72 + c] = Wk[idx];
        sW[1 * 64 * 72 + i * 72 + c] = Wq[idx];
        sW[2 * 64 * 72 + i * 72 + c] = Ww[idx];
    }
    const int base = blockIdx.x * 32;
    for (int idx = tid; idx < 32 * 64; idx += 192) {
        const int n = idx >> 6, c = idx & 63;
        const int gn = base + n;
        sA[n * 72 + c] = (gn < N) ? h[(size_t)gn * 64 + c] : 0.f;
    }
    __syncthreads();

    const int wid  = tid >> 5;
    const int lane = tid & 31;
    const int sel  = wid >> 1;          // 0:Wk 1:Wq 2:Ww
    const int mh   = wid & 1;           // m-half (16 nodes)
    const int g    = lane >> 2;         // 0..7
    const int t4   = lane & 3;          // 0..3

    float4 acc[8];
#pragma unroll
    for (int nt = 0; nt < 8; nt++) acc[nt] = make_float4(0.f, 0.f, 0.f, 0.f);

    const float* wm = sW + sel * 64 * 72;

#pragma unroll
    for (int ks = 0; ks < 8; ks++) {
        // A fragment (m16 x k8), rows = mh*16 + {g, g+8}, cols = ks*8 + {t4, t4+4}
        const int r0 = (mh * 16 + g) * 72 + ks * 8 + t4;
        const int r1 = (mh * 16 + g + 8) * 72 + ks * 8 + t4;
        const float a0f = sA[r0],     a1f = sA[r1];
        const float a2f = sA[r0 + 4], a3f = sA[r1 + 4];

        unsigned ahi[4], alo[4];
        ahi[0] = to_tf32(a0f); alo[0] = to_tf32(a0f - __uint_as_float(ahi[0]));
        ahi[1] = to_tf32(a1f); alo[1] = to_tf32(a1f - __uint_as_float(ahi[1]));
        ahi[2] = to_tf32(a2f); alo[2] = to_tf32(a2f - __uint_as_float(ahi[2]));
        ahi[3] = to_tf32(a3f); alo[3] = to_tf32(a3f - __uint_as_float(ahi[3]));

#pragma unroll
        for (int nt = 0; nt < 8; nt++) {
            // B fragment (k8 x n8): k = ks*8 + {t4, t4+4}, n = nt*8 + g
            const float b0f = wm[(ks * 8 + t4) * 72 + nt * 8 + g];
            const float b1f = wm[(ks * 8 + t4 + 4) * 72 + nt * 8 + g];
            unsigned bhi[2], blo[2];
            bhi[0] = to_tf32(b0f); blo[0] = to_tf32(b0f - __uint_as_float(bhi[0]));
            bhi[1] = to_tf32(b1f); blo[1] = to_tf32(b1f - __uint_as_float(bhi[1]));

            mma_tf32(acc[nt], ahi, bhi);
            mma_tf32(acc[nt], ahi, blo);
            mma_tf32(acc[nt], alo, bhi);
        }
    }

    // store: c0,c1 -> (row g, col t4*2 | +1); c2,c3 -> (row g+8)
    const int gn0 = base + mh * 16 + g;
    const int gn1 = gn0 + 8;
#pragma unroll
    for (int nt = 0; nt < 8; nt++) {
        const int col = nt * 8 + t4 * 2;
        if (sel == 0) {
            if (gn0 < N) *(float2*)&g_kw[(size_t)gn0 * 128 + col] = make_float2(acc[nt].x, acc[nt].y);
            if (gn1 < N) *(float2*)&g_kw[(size_t)gn1 * 128 + col] = make_float2(acc[nt].z, acc[nt].w);
        } else if (sel == 1) {
            if (gn0 < N) *(float2*)&g_q[(size_t)gn0 * 64 + col] = make_float2(acc[nt].x, acc[nt].y);
            if (gn1 < N) *(float2*)&g_q[(size_t)gn1 * 64 + col] = make_float2(acc[nt].z, acc[nt].w);
        } else {
            if (gn0 < N) *(float2*)&g_kw[(size_t)gn0 * 128 + 64 + col] = make_float2(acc[nt].x, acc[nt].y);
            if (gn1 < N) *(float2*)&g_kw[(size_t)gn1 * 128 + 64 + col] = make_float2(acc[nt].z, acc[nt].w);
        }
    }
}

// ---------------------------------------------------------------------------
// Single-pass decoupled-lookback exclusive scan of g_cnt -> g_roff/g_cur.
// g_state[b] = (value<<2) | flag; flag 1 = aggregate, 2 = inclusive prefix.
// All 391 blocks are co-resident -> spin is safe.
// ---------------------------------------------------------------------------
__global__ __launch_bounds__(256) void scan_lb_kernel(int N, int E)
{
    __shared__ int wsum[8];
    __shared__ int sagg;
    __shared__ int sexc;
    const int t = threadIdx.x, lane = t & 31, wd = t >> 5;
    const int bid = blockIdx.x;
    const int i = bid * 256 + t;
    const int v = (i < N) ? g_cnt[i] : 0;

    int x = v;
#pragma unroll
    for (int off = 1; off < 32; off <<= 1) {
        int y = __shfl_up_sync(0xffffffffu, x, off);
        if (lane >= off) x += y;
    }
    if (lane == 31) wsum[wd] = x;
    __syncthreads();
    if (t < 8) {
        int w = wsum[t];
        int xs = w;
#pragma unroll
        for (int off = 1; off < 8; off <<= 1) {
            int y = __shfl_up_sync(0x000000ffu, xs, off);
            if (t >= off) xs += y;
        }
        wsum[t] = xs - w;                 // exclusive warp offset
        if (t == 7) {
            sagg = xs;                    // block aggregate
            atomicExch(&g_state[bid], (xs << 2) | 1);
        }
    }
    __syncthreads();

    if (t == 0) {
        int exc = 0;
        if (bid > 0) {
            int j = bid - 1;
            while (true) {
                int s = atomicAdd(&g_state[j], 0);
                if ((s & 3) == 0) continue;
                exc += (s >> 2);
                if ((s & 3) == 2) break;
                j--;
            }
        }
        atomicExch(&g_state[bid], ((exc + sagg) << 2) | 2);
        sexc = exc;
    }
    __syncthreads();

    const int r = sexc + wsum[wd] + x - v;
    if (i < N) { g_roff[i] = r; g_cur[i] = r; }
    if (bid == 0 && t == 0) g_roff[N] = E;
}

__global__ void scatter_kernel(const int* __restrict__ src,
                               const int* __restrict__ dst, int E)
{
    int i = blockIdx.x * blockDim.x + threadIdx.x;
    if (i < E) {
        int p = atomicAdd(&g_cur[dst[i]], 1);
        g_esrc[p] = src[i];
    }
}

// ---------------------------------------------------------------------------
// Fused edge-softmax + aggregation (R2 form: minimal L1-return bytes/edge).
// One warp per destination node; 512 B/edge through L1; broadcast shuffles.
// ---------------------------------------------------------------------------
__global__ __launch_bounds__(256) void gather_kernel(
    const float* __restrict__ b,
    float* __restrict__ out,
    int N)
{
    const int w    = (blockIdx.x * 256 + threadIdx.x) >> 5;
    const int lane = threadIdx.x & 31;
    if (w >= N) return;
    const int n = w;

    const float2 q2 = ((const float2*)(g_q + (size_t)n * 64))[lane];
    const int p0 = g_roff[n];
    const int p1 = g_roff[n + 1];

    float2 acc0 = make_float2(0.f, 0.f), acc1 = acc0, acc2 = acc0, acc3 = acc0;
    float z0 = 0.f, z1 = 0.f, z2 = 0.f, z3 = 0.f;

    if (p0 < p1) {
        int s = g_esrc[p0];
        const float2* kp = (const float2*)(g_kw + (size_t)s * 128);
        float2 k2 = kp[lane];
        float2 w2 = kp[lane + 32];

        for (int p = p0; p < p1; p++) {
            float2 k2n = k2, w2n = w2;
            if (p + 1 < p1) {
                int sn = g_esrc[p + 1];
                const float2* kpn = (const float2*)(g_kw + (size_t)sn * 128);
                k2n = kpn[lane];
                w2n = kpn[lane + 32];
            }

            float prod = k2.x * q2.x + k2.y * q2.y;
            prod += __shfl_xor_sync(0xffffffffu, prod, 4);
            prod += __shfl_xor_sync(0xffffffffu, prod, 2);
            prod += __shfl_xor_sync(0xffffffffu, prod, 1);
            const float pe = __expf(prod);
            const float e0 = __shfl_sync(0xffffffffu, pe, 0);
            const float e1 = __shfl_sync(0xffffffffu, pe, 8);
            const float e2 = __shfl_sync(0xffffffffu, pe, 16);
            const float e3 = __shfl_sync(0xffffffffu, pe, 24);

            z0 += e0; z1 += e1; z2 += e2; z3 += e3;
            acc0.x += e0 * w2.x; acc0.y += e0 * w2.y;
            acc1.x += e1 * w2.x; acc1.y += e1 * w2.y;
            acc2.x += e2 * w2.x; acc2.y += e2 * w2.y;
            acc3.x += e3 * w2.x; acc3.y += e3 * w2.y;

            k2 = k2n; w2 = w2n;
        }
    }

    const float i0 = (z0 > 0.f) ? 1.f / z0 : 0.f;
    const float i1 = (z1 > 0.f) ? 1.f / z1 : 0.f;
    const float i2 = (z2 > 0.f) ? 1.f / z2 : 0.f;
    const float i3 = (z3 > 0.f) ? 1.f / z3 : 0.f;

    const float2 bb = ((const float2*)b)[lane];
    float* op = out + (size_t)n * 256;
    ((float2*)(op      ))[lane] = make_float2(acc0.x * i0 + bb.x, acc0.y * i0 + bb.y);
    ((float2*)(op +  64))[lane] = make_float2(acc1.x * i1 + bb.x, acc1.y * i1 + bb.y);
    ((float2*)(op + 128))[lane] = make_float2(acc2.x * i2 + bb.x, acc2.y * i2 + bb.y);
    ((float2*)(op + 192))[lane] = make_float2(acc3.x * i3 + bb.x, acc3.y * i3 + bb.y);
}

// ---------------------------------------------------------------------------
extern "C" void kernel_launch(void* const* d_in, const int* in_sizes, int n_in,
                              void* d_out, int out_size)
{
    const float* h   = (const float*)d_in[0];
    const int*   src = (const int*)  d_in[1];
    const int*   dst = (const int*)  d_in[2];
    const float* Wk  = (const float*)d_in[3];
    const float* Wq  = (const float*)d_in[4];
    const float* Ww  = (const float*)d_in[5];
    const float* b   = (const float*)d_in[6];
    float*       out = (float*)d_out;

    const int N  = in_sizes[0] / 64;
    const int E  = in_sizes[1];
    const int nb = (N + 255) / 256;

    static void* cnt_ptr = nullptr;
    static void* state_ptr = nullptr;
    if (cnt_ptr == nullptr) {
        cudaGetSymbolAddress(&cnt_ptr, g_cnt);
        cudaGetSymbolAddress(&state_ptr, g_state);
    }

    cudaMemsetAsync(cnt_ptr, 0, (size_t)N * sizeof(int));
    cudaMemsetAsync(state_ptr, 0, (size_t)nb * sizeof(int));
    gemm_mma_hist_kernel<<<(N + 31) / 32, 192>>>(h, Wk, Wq, Ww, dst, N, E);
    scan_lb_kernel<<<nb, 256>>>(N, E);
    scatter_kernel<<<(E + 255) / 256, 256>>>(src, dst, E);
    gather_kernel<<<(N + 7) / 8, 256>>>(b, out, N);
}

// round 8
// speedup vs baseline: 1.2044x; 1.0002x over previous
#include <cuda_runtime.h>

#define NN 100000
#define EE 1600000

// Scratch (allocation-free rule: __device__ globals)
__device__ float g_kw  [NN * 128];  // interleaved: [n][0:64]=k row, [n][64:128]=hw row
__device__ float g_q   [NN * 64];
__device__ int   g_cnt [NN];
__device__ int   g_roff[NN + 1];
__device__ int   g_cur [NN];
__device__ int   g_state[512];      // decoupled-lookback block state
__device__ int   g_esrc[EE];

// ---- tf32 helpers ----------------------------------------------------------
__device__ __forceinline__ unsigned to_tf32(float x)
{
    unsigned r; asm("cvt.rna.tf32.f32 %0, %1;" : "=r"(r) : "f"(x)); return r;
}
__device__ __forceinline__ void mma_tf32(float4& d, const unsigned* a, const unsigned* b)
{
    asm volatile(
        "mma.sync.aligned.m16n8k8.row.col.f32.tf32.tf32.f32 "
        "{%0,%1,%2,%3}, {%4,%5,%6,%7}, {%8,%9}, {%0,%1,%2,%3};"
        : "+f"(d.x), "+f"(d.y), "+f"(d.z), "+f"(d.w)
        : "r"(a[0]), "r"(a[1]), "r"(a[2]), "r"(a[3]), "r"(b[0]), "r"(b[1]));
}

// ---------------------------------------------------------------------------
// k = h@Wk, q = h@Wq, hw = h@W via 3xTF32 tensor-core MMA (fp32-class
// accuracy), PLUS the dst-histogram (RED ops hide under tensor work).
// 192 threads = 6 warps = 3 matrices x 2 m-halves. (R5-proven.)
// ---------------------------------------------------------------------------
__global__ __launch_bounds__(192) void gemm_mma_hist_kernel(
    const float* __restrict__ h,
    const float* __restrict__ Wk,
    const float* __restrict__ Wq,
    const float* __restrict__ Ww,
    const int*   __restrict__ dst,
    int N, int E)
{
    __shared__ float sA[32 * 72];        // sA[node][kdim]
    __shared__ float sW[3 * 64 * 72];    // sW[sel][kdim][col]

    const int tid = threadIdx.x;

    // --- histogram slice (fire-and-forget L2 reductions) ---
    {
        const int eslice = (E + gridDim.x - 1) / gridDim.x;
        const int e0 = blockIdx.x * eslice;
        const int e1 = (e0 + eslice < E) ? e0 + eslice : E;
        for (int i = e0 + tid; i < e1; i += 192)
            atomicAdd(&g_cnt[dst[i]], 1);
    }

    for (int idx = tid; idx < 64 * 64; idx += 192) {
        const int i = idx >> 6, c = idx & 63;
        sW[0 * 64 * 72 + i * 72 + c] = Wk[idx];
        sW[1 * 64 * 72 + i * 72 + c] = Wq[idx];
        sW[2 * 64 * 72 + i * 72 + c] = Ww[idx];
    }
    const int base = blockIdx.x * 32;
    for (int idx = tid; idx < 32 * 64; idx += 192) {
        const int n = idx >> 6, c = idx & 63;
        const int gn = base + n;
        sA[n * 72 + c] = (gn < N) ? h[(size_t)gn * 64 + c] : 0.f;
    }
    __syncthreads();

    const int wid  = tid >> 5;
    const int lane = tid & 31;
    const int sel  = wid >> 1;          // 0:Wk 1:Wq 2:Ww
    const int mh   = wid & 1;           // m-half (16 nodes)
    const int g    = lane >> 2;         // 0..7
    const int t4   = lane & 3;          // 0..3

    float4 acc[8];
#pragma unroll
    for (int nt = 0; nt < 8; nt++) acc[nt] = make_float4(0.f, 0.f, 0.f, 0.f);

    const float* wm = sW + sel * 64 * 72;

#pragma unroll
    for (int ks = 0; ks < 8; ks++) {
        const int r0 = (mh * 16 + g) * 72 + ks * 8 + t4;
        const int r1 = (mh * 16 + g + 8) * 72 + ks * 8 + t4;
        const float a0f = sA[r0],     a1f = sA[r1];
        const float a2f = sA[r0 + 4], a3f = sA[r1 + 4];

        unsigned ahi[4], alo[4];
        ahi[0] = to_tf32(a0f); alo[0] = to_tf32(a0f - __uint_as_float(ahi[0]));
        ahi[1] = to_tf32(a1f); alo[1] = to_tf32(a1f - __uint_as_float(ahi[1]));
        ahi[2] = to_tf32(a2f); alo[2] = to_tf32(a2f - __uint_as_float(ahi[2]));
        ahi[3] = to_tf32(a3f); alo[3] = to_tf32(a3f - __uint_as_float(ahi[3]));

#pragma unroll
        for (int nt = 0; nt < 8; nt++) {
            const float b0f = wm[(ks * 8 + t4) * 72 + nt * 8 + g];
            const float b1f = wm[(ks * 8 + t4 + 4) * 72 + nt * 8 + g];
            unsigned bhi[2], blo[2];
            bhi[0] = to_tf32(b0f); blo[0] = to_tf32(b0f - __uint_as_float(bhi[0]));
            bhi[1] = to_tf32(b1f); blo[1] = to_tf32(b1f - __uint_as_float(bhi[1]));

            mma_tf32(acc[nt], ahi, bhi);
            mma_tf32(acc[nt], ahi, blo);
            mma_tf32(acc[nt], alo, bhi);
        }
    }

    const int gn0 = base + mh * 16 + g;
    const int gn1 = gn0 + 8;
#pragma unroll
    for (int nt = 0; nt < 8; nt++) {
        const int col = nt * 8 + t4 * 2;
        if (sel == 0) {
            if (gn0 < N) *(float2*)&g_kw[(size_t)gn0 * 128 + col] = make_float2(acc[nt].x, acc[nt].y);
            if (gn1 < N) *(float2*)&g_kw[(size_t)gn1 * 128 + col] = make_float2(acc[nt].z, acc[nt].w);
        } else if (sel == 1) {
            if (gn0 < N) *(float2*)&g_q[(size_t)gn0 * 64 + col] = make_float2(acc[nt].x, acc[nt].y);
            if (gn1 < N) *(float2*)&g_q[(size_t)gn1 * 64 + col] = make_float2(acc[nt].z, acc[nt].w);
        } else {
            if (gn0 < N) *(float2*)&g_kw[(size_t)gn0 * 128 + 64 + col] = make_float2(acc[nt].x, acc[nt].y);
            if (gn1 < N) *(float2*)&g_kw[(size_t)gn1 * 128 + 64 + col] = make_float2(acc[nt].z, acc[nt].w);
        }
    }
}

// ---------------------------------------------------------------------------
// Single-pass decoupled-lookback exclusive scan (R5-proven: runs alone on the
// stream, all 391 blocks co-resident).
// ---------------------------------------------------------------------------
__global__ __launch_bounds__(256) void scan_lb_kernel(int N, int E)
{
    __shared__ int wsum[8];
    __shared__ int sagg;
    __shared__ int sexc;
    const int t = threadIdx.x, lane = t & 31, wd = t >> 5;
    const int bid = blockIdx.x;
    const int i = bid * 256 + t;
    const int v = (i < N) ? g_cnt[i] : 0;

    int x = v;
#pragma unroll
    for (int off = 1; off < 32; off <<= 1) {
        int y = __shfl_up_sync(0xffffffffu, x, off);
        if (lane >= off) x += y;
    }
    if (lane == 31) wsum[wd] = x;
    __syncthreads();
    if (t < 8) {
        int w = wsum[t];
        int xs = w;
#pragma unroll
        for (int off = 1; off < 8; off <<= 1) {
            int y = __shfl_up_sync(0x000000ffu, xs, off);
            if (t >= off) xs += y;
        }
        wsum[t] = xs - w;
        if (t == 7) {
            sagg = xs;
            atomicExch(&g_state[bid], (xs << 2) | 1);
        }
    }
    __syncthreads();

    if (t == 0) {
        int exc = 0;
        if (bid > 0) {
            int j = bid - 1;
            while (true) {
                int s = atomicAdd(&g_state[j], 0);
                if ((s & 3) == 0) continue;
                exc += (s >> 2);
                if ((s & 3) == 2) break;
                j--;
            }
        }
        atomicExch(&g_state[bid], ((exc + sagg) << 2) | 2);
        sexc = exc;
    }
    __syncthreads();

    const int r = sexc + wsum[wd] + x - v;
    if (i < N) { g_roff[i] = r; g_cur[i] = r; }
    if (bid == 0 && t == 0) g_roff[N] = E;
}

__global__ void scatter_kernel(const int* __restrict__ src,
                               const int* __restrict__ dst, int E)
{
    int i = blockIdx.x * blockDim.x + threadIdx.x;
    if (i < E) {
        int p = atomicAdd(&g_cur[dst[i]], 1);
        g_esrc[p] = src[i];
    }
}

// ---------------------------------------------------------------------------
// Fused edge-softmax + aggregation. One warp per destination node, TWO edges
// per iteration (one per 16-lane half). Lane fl owns features 4fl..4fl+3;
// head = fl>>2. Dot reduce = 2 xor shuffles; cross-head exchange = 3 parallel
// xor shuffles with RELATIVE accumulators (acc[j] belongs to head hh^j).
// Cross-half combine at the end. No atomics.
// ---------------------------------------------------------------------------
__global__ __launch_bounds__(256) void gather_kernel(
    const float* __restrict__ b,
    float* __restrict__ out,
    int N)
{
    const int n    = (blockIdx.x * 256 + threadIdx.x) >> 5;
    const int lane = threadIdx.x & 31;
    if (n >= N) return;
    const int half = lane >> 4;     // which edge of the pair
    const int fl   = lane & 15;     // feature-lane: 4 floats
    const int hh   = fl >> 2;       // own head

    const float4 q4 = *(const float4*)(g_q + (size_t)n * 64 + 4 * fl);
    const int p0 = g_roff[n];
    const int p1 = g_roff[n + 1];

    float4 a0 = make_float4(0.f, 0.f, 0.f, 0.f), a1 = a0, a2 = a0, a3 = a0;
    float z0 = 0.f, z1 = 0.f, z2 = 0.f, z3 = 0.f;

    // prefetch first pair
    const int pp = p0 + half;
    const int s0 = (pp < p1) ? g_esrc[pp] : 0;
    const float* row = g_kw + (size_t)s0 * 128;
    float4 k4 = *(const float4*)(row + 4 * fl);
    float4 w4 = *(const float4*)(row + 64 + 4 * fl);

    for (int base = p0; base < p1; base += 2) {
        const bool v = (base + half) < p1;
        const float4 k4c = k4, w4c = w4;

        const int pn = base + 2 + half;
        if (pn < p1) {
            const int sn = g_esrc[pn];
            const float* rn = g_kw + (size_t)sn * 128;
            k4 = *(const float4*)(rn + 4 * fl);
            w4 = *(const float4*)(rn + 64 + 4 * fl);
        }

        float prod = k4c.x * q4.x + k4c.y * q4.y + k4c.z * q4.z + k4c.w * q4.w;
        prod += __shfl_xor_sync(0xffffffffu, prod, 1);
        prod += __shfl_xor_sync(0xffffffffu, prod, 2);
        const float e  = v ? __expf(prod) : 0.f;               // own head
        const float eA = __shfl_xor_sync(0xffffffffu, e, 4);   // head hh^1
        const float eB = __shfl_xor_sync(0xffffffffu, e, 8);   // head hh^2
        const float eC = __shfl_xor_sync(0xffffffffu, e, 12);  // head hh^3

        z0 += e; z1 += eA; z2 += eB; z3 += eC;
        a0.x += e  * w4c.x; a0.y += e  * w4c.y; a0.z += e  * w4c.z; a0.w += e  * w4c.w;
        a1.x += eA * w4c.x; a1.y += eA * w4c.y; a1.z += eA * w4c.z; a1.w += eA * w4c.w;
        a2.x += eB * w4c.x; a2.y += eB * w4c.y; a2.z += eB * w4c.z; a2.w += eB * w4c.w;
        a3.x += eC * w4c.x; a3.y += eC * w4c.y; a3.z += eC * w4c.z; a3.w += eC * w4c.w;
    }

    // cross-half combine (lane fl of both halves hold same (head,feature) slice)
    a0.x += __shfl_xor_sync(0xffffffffu, a0.x, 16);
    a0.y += __shfl_xor_sync(0xffffffffu, a0.y, 16);
    a0.z += __shfl_xor_sync(0xffffffffu, a0.z, 16);
    a0.w += __shfl_xor_sync(0xffffffffu, a0.w, 16);
    a1.x += __shfl_xor_sync(0xffffffffu, a1.x, 16);
    a1.y += __shfl_xor_sync(0xffffffffu, a1.y, 16);
    a1.z += __shfl_xor_sync(0xffffffffu, a1.z, 16);
    a1.w += __shfl_xor_sync(0xffffffffu, a1.w, 16);
    a2.x += __shfl_xor_sync(0xffffffffu, a2.x, 16);
    a2.y += __shfl_xor_sync(0xffffffffu, a2.y, 16);
    a2.z += __shfl_xor_sync(0xffffffffu, a2.z, 16);
    a2.w += __shfl_xor_sync(0xffffffffu, a2.w, 16);
    a3.x += __shfl_xor_sync(0xffffffffu, a3.x, 16);
    a3.y += __shfl_xor_sync(0xffffffffu, a3.y, 16);
    a3.z += __shfl_xor_sync(0xffffffffu, a3.z, 16);
    a3.w += __shfl_xor_sync(0xffffffffu, a3.w, 16);
    z0 += __shfl_xor_sync(0xffffffffu, z0, 16);
    z1 += __shfl_xor_sync(0xffffffffu, z1, 16);
    z2 += __shfl_xor_sync(0xffffffffu, z2, 16);
    z3 += __shfl_xor_sync(0xffffffffu, z3, 16);

    if (half == 0) {
        const float i0 = (z0 > 0.f) ? 1.f / z0 : 0.f;
        const float i1 = (z1 > 0.f) ? 1.f / z1 : 0.f;
        const float i2 = (z2 > 0.f) ? 1.f / z2 : 0.f;
        const float i3 = (z3 > 0.f) ? 1.f / z3 : 0.f;
        const float4 bb = *(const float4*)(b + 4 * fl);
        float* op = out + (size_t)n * 256 + 4 * fl;

        *(float4*)(op + (size_t)(hh     ) * 64) =
            make_float4(a0.x * i0 + bb.x, a0.y * i0 + bb.y, a0.z * i0 + bb.z, a0.w * i0 + bb.w);
        *(float4*)(op + (size_t)(hh ^ 1) * 64) =
            make_float4(a1.x * i1 + bb.x, a1.y * i1 + bb.y, a1.z * i1 + bb.z, a1.w * i1 + bb.w);
        *(float4*)(op + (size_t)(hh ^ 2) * 64) =
            make_float4(a2.x * i2 + bb.x, a2.y * i2 + bb.y, a2.z * i2 + bb.z, a2.w * i2 + bb.w);
        *(float4*)(op + (size_t)(hh ^ 3) * 64) =
            make_float4(a3.x * i3 + bb.x, a3.y * i3 + bb.y, a3.z * i3 + bb.z, a3.w * i3 + bb.w);
    }
}

// ---------------------------------------------------------------------------
extern "C" void kernel_launch(void* const* d_in, const int* in_sizes, int n_in,
                              void* d_out, int out_size)
{
    const float* h   = (const float*)d_in[0];
    const int*   src = (const int*)  d_in[1];
    const int*   dst = (const int*)  d_in[2];
    const float* Wk  = (const float*)d_in[3];
    const float* Wq  = (const float*)d_in[4];
    const float* Ww  = (const float*)d_in[5];
    const float* b   = (const float*)d_in[6];
    float*       out = (float*)d_out;

    const int N  = in_sizes[0] / 64;
    const int E  = in_sizes[1];
    const int nb = (N + 255) / 256;

    static void* cnt_ptr = nullptr;
    static void* state_ptr = nullptr;
    if (cnt_ptr == nullptr) {
        cudaGetSymbolAddress(&cnt_ptr, g_cnt);
        cudaGetSymbolAddress(&state_ptr, g_state);
    }

    cudaMemsetAsync(cnt_ptr, 0, (size_t)N * sizeof(int));
    cudaMemsetAsync(state_ptr, 0, (size_t)nb * sizeof(int));
    gemm_mma_hist_kernel<<<(N + 31) / 32, 192>>>(h, Wk, Wq, Ww, dst, N, E);
    scan_lb_kernel<<<nb, 256>>>(N, E);
    scatter_kernel<<<(E + 255) / 256, 256>>>(src, dst, E);
    gather_kernel<<<(N + 7) / 8, 256>>>(b, out, N);
}